// round 1
// baseline (speedup 1.0000x reference)
#include <cuda_runtime.h>
#include <math.h>

// Problem constants (fixed by the reference)
#define BB 4
#define CC 128
#define HH 240
#define WW 320
#define NN 1024
#define NPTS (BB * NN)          // 4096 points
#define EPSV 1e-9f
#define HWSZ (HH * WW)          // 76800

// Scratch for cross-block reduction (no cudaMalloc allowed)
__device__ double g_e1_sum;
__device__ double g_ld_sum;

__global__ void gn_init_kernel() {
    g_e1_sum = 0.0;
    g_ld_sum = 0.0;
}

// One warp per point. Lanes stride over channels (4 channels/lane).
__global__ __launch_bounds__(256) void gn_main_kernel(
    const float* __restrict__ Fa,
    const float* __restrict__ Fb,
    const float* __restrict__ ma,
    const float* __restrict__ mb,
    const float* __restrict__ nz)
{
    const int gwarp = (blockIdx.x * 256 + threadIdx.x) >> 5;   // point index, 0..4095
    const int lane  = threadIdx.x & 31;
    const int b     = gwarp >> 10;                              // / NN
    const int pi    = gwarp;                                    // b*NN + n

    // ---- per-point coordinates (uniform across warp) ----
    const float xa  = ma[pi * 2 + 0] * 0.125f;
    const float ya  = ma[pi * 2 + 1] * 0.125f;
    const float ubx = mb[pi * 2 + 0] * 0.125f;
    const float uby = mb[pi * 2 + 1] * 0.125f;
    const float xsx = 2.0f * nz[pi * 2 + 0] - 1.0f + ubx;
    const float xsy = 2.0f * nz[pi * 2 + 1] - 1.0f + uby;

    // ---- F_a bilinear setup ----
    const float fax0 = floorf(xa), fay0 = floorf(ya);
    const float wxa = xa - fax0, wya = ya - fay0;
    int ax0 = min(max((int)fax0, 0), WW - 1);
    int ax1 = min(ax0 + 1, WW - 1);
    int ay0 = min(max((int)fay0, 0), HH - 1);
    int ay1 = min(ay0 + 1, HH - 1);
    const float wa00 = (1.f - wxa) * (1.f - wya);
    const float wa01 = wxa * (1.f - wya);
    const float wa10 = (1.f - wxa) * wya;
    const float wa11 = wxa * wya;
    const int aoff00 = ay0 * WW + ax0, aoff01 = ay0 * WW + ax1;
    const int aoff10 = ay1 * WW + ax0, aoff11 = ay1 * WW + ax1;

    // ---- F_b bilinear + on-the-fly gradient setup ----
    const float fbx0 = floorf(xsx), fby0 = floorf(xsy);
    const float wxb = xsx - fbx0, wyb = xsy - fby0;
    int bx0 = min(max((int)fbx0, 0), WW - 1);
    int bx1 = min(bx0 + 1, WW - 1);
    int by0 = min(max((int)fby0, 0), HH - 1);
    int by1 = min(by0 + 1, HH - 1);
    // Column set {x0-1, x0, x1, x1+1} (clamped) and row set likewise cover every
    // sample required by f_s, gx, gy at all 4 bilinear corners.
    int cxs0 = max(bx0 - 1, 0);
    int cxs3 = min(bx1 + 1, WW - 1);
    int rys0 = max(by0 - 1, 0);
    int rys3 = min(by1 + 1, HH - 1);
    // left neighbor of x1 is x0 when x1>x0, else (x0==W-1) it's column 0 of our set
    const int sx = (bx1 > bx0) ? 1 : 0;
    const int sy = (by1 > by0) ? 1 : 0;
    const float wb00 = (1.f - wxb) * (1.f - wyb);
    const float wb01 = wxb * (1.f - wyb);
    const float wb10 = (1.f - wxb) * wyb;
    const float wb11 = wxb * wyb;

    int cxs[4] = { cxs0, bx0, bx1, cxs3 };
    int roff[4] = { rys0 * WW, by0 * WW, by1 * WW, rys3 * WW };

    const float* __restrict__ FaB = Fa + (size_t)b * CC * HWSZ;
    const float* __restrict__ FbB = Fb + (size_t)b * CC * HWSZ;

    // ---- channel accumulation ----
    float s_tt = 0.f, s_ss = 0.f, s_xs = 0.f, s_xt = 0.f, s_ys = 0.f,
          s_yt = 0.f, s_xx = 0.f, s_xy = 0.f, s_yy = 0.f;

    #pragma unroll
    for (int it = 0; it < CC / 32; it++) {
        const int cc = lane + it * 32;
        const float* p = FbB + cc * HWSZ;
        float v[4][4];
        #pragma unroll
        for (int r = 0; r < 4; r++) {
            #pragma unroll
            for (int k = 0; k < 4; k++)
                v[r][k] = __ldg(p + roff[r] + cxs[k]);
        }
        const float* pa = FaB + cc * HWSZ;
        const float a00 = __ldg(pa + aoff00);
        const float a01 = __ldg(pa + aoff01);
        const float a10 = __ldg(pa + aoff10);
        const float a11 = __ldg(pa + aoff11);

        const float fs = wb00 * v[1][1] + wb01 * v[1][2] + wb10 * v[2][1] + wb11 * v[2][2];
        const float Jx = 0.5f * (wb00 * (v[1][2] - v[1][0]) + wb01 * (v[1][3] - v[1][sx]) +
                                 wb10 * (v[2][2] - v[2][0]) + wb11 * (v[2][3] - v[2][sx]));
        const float Jy = 0.5f * (wb00 * (v[2][1] - v[0][1]) + wb01 * (v[2][2] - v[0][2]) +
                                 wb10 * (v[3][1] - v[sy][1]) + wb11 * (v[3][2] - v[sy][2]));
        const float ft = wa00 * a00 + wa01 * a01 + wa10 * a10 + wa11 * a11;

        s_tt += ft * ft;  s_ss += fs * fs;
        s_xs += Jx * fs;  s_xt += Jx * ft;
        s_ys += Jy * fs;  s_yt += Jy * ft;
        s_xx += Jx * Jx;  s_xy += Jx * Jy;  s_yy += Jy * Jy;
    }

    // ---- warp reduction of the 9 sums ----
    #pragma unroll
    for (int o = 16; o > 0; o >>= 1) {
        s_tt += __shfl_xor_sync(0xFFFFFFFFu, s_tt, o);
        s_ss += __shfl_xor_sync(0xFFFFFFFFu, s_ss, o);
        s_xs += __shfl_xor_sync(0xFFFFFFFFu, s_xs, o);
        s_xt += __shfl_xor_sync(0xFFFFFFFFu, s_xt, o);
        s_ys += __shfl_xor_sync(0xFFFFFFFFu, s_ys, o);
        s_yt += __shfl_xor_sync(0xFFFFFFFFu, s_yt, o);
        s_xx += __shfl_xor_sync(0xFFFFFFFFu, s_xx, o);
        s_xy += __shfl_xor_sync(0xFFFFFFFFu, s_xy, o);
        s_yy += __shfl_xor_sync(0xFFFFFFFFu, s_yy, o);
    }

    __shared__ double sh_e1[8];
    __shared__ double sh_ld[8];
    const int widx = threadIdx.x >> 5;

    if (lane == 0) {
        // ---- per-point epilogue (2x2 GN step) ----
        const float invnt = 1.f / fmaxf(sqrtf(s_tt), 1e-12f);
        const float invns = 1.f / fmaxf(sqrtf(s_ss), 1e-12f);
        // b = J^T r, with r = f_s/||f_s|| - f_t/||f_t||
        const float bxv = s_xs * invns - s_xt * invnt;
        const float byv = s_ys * invns - s_yt * invnt;
        const float aH = s_xx + EPSV;
        const float dH = s_yy + EPSV;
        const float bH = s_xy;
        const float det = aH * dH - bH * bH;
        const float inv_det = 1.f / det;
        // delta = Hinv @ b
        const float ddx = (dH * bxv - bH * byv) * inv_det;
        const float ddy = (aH * byv - bH * bxv) * inv_det;
        // diff = ub - miu = (ub - xs) + delta
        const float dx = (ubx - xsx) + ddx;
        const float dy = (uby - xsy) + ddy;
        sh_e1[widx] = 0.5 * (double)(aH * dx * dx + 2.f * bH * dx * dy + dH * dy * dy);
        sh_ld[widx] = log((double)det);
    }
    __syncthreads();

    if (threadIdx.x == 0) {
        double e1 = 0.0, ld = 0.0;
        #pragma unroll
        for (int i = 0; i < 8; i++) { e1 += sh_e1[i]; ld += sh_ld[i]; }
        atomicAdd(&g_e1_sum, e1);
        atomicAdd(&g_ld_sum, ld);
    }
}

__global__ void gn_finalize_kernel(float* __restrict__ out) {
    const double e1 = g_e1_sum;
    const double e2 = (double)NPTS * log(2.0 * M_PI) - 0.5 * g_ld_sum;
    const double e  = 1.0 * e1 + (2.0 / 7.0) * e2;   // E1_LAMDA*e1 + E2_LAMDA*e2
    out[0] = (float)(0.3 * e);                        // GN_LAMDA * e
    out[1] = (float)e1;
    out[2] = (float)e2;
}

extern "C" void kernel_launch(void* const* d_in, const int* in_sizes, int n_in,
                              void* d_out, int out_size) {
    const float* Fa = (const float*)d_in[0];
    const float* Fb = (const float*)d_in[1];
    const float* ma = (const float*)d_in[2];
    const float* mb = (const float*)d_in[3];
    const float* nz = (const float*)d_in[4];
    float* out = (float*)d_out;

    gn_init_kernel<<<1, 1>>>();
    gn_main_kernel<<<NPTS / 8, 256>>>(Fa, Fb, ma, mb, nz);
    gn_finalize_kernel<<<1, 1>>>(out);
}

// round 3
// speedup vs baseline: 1.0482x; 1.0482x over previous
#include <cuda_runtime.h>
#include <math.h>

// Problem constants (fixed by the reference)
#define BB 4
#define CC 128
#define HH 240
#define WW 320
#define NN 1024
#define NPTS (BB * NN)          // 4096 points
#define EPSV 1e-9f
#define HWSZ (HH * WW)          // 76800
#define PTS_PER_BLOCK 4
#define NBLOCKS (NPTS / PTS_PER_BLOCK)   // 1024

// Per-block partial sums (every slot overwritten each launch -> no init kernel)
__device__ double g_pe1[NBLOCKS];
__device__ double g_pld[NBLOCKS];

// 2 warps per point (64 channels each, 2 ch/lane -> 40 loads/warp, under the
// ~55-outstanding-LDG per-warp cap). 8 warps / 4 points per block.
__global__ __launch_bounds__(256) void gn_main_kernel(
    const float* __restrict__ Fa,
    const float* __restrict__ Fb,
    const float* __restrict__ ma,
    const float* __restrict__ mb,
    const float* __restrict__ nz)
{
    const int w    = threadIdx.x >> 5;       // warp in block, 0..7
    const int lane = threadIdx.x & 31;
    const int q    = w >> 1;                 // point in block, 0..3
    const int half = w & 1;                  // channel half
    const int pi   = blockIdx.x * PTS_PER_BLOCK + q;   // global point 0..4095
    const int b    = pi >> 10;               // batch

    // ---- per-point coordinates (uniform across warp) ----
    const float xa  = ma[pi * 2 + 0] * 0.125f;
    const float ya  = ma[pi * 2 + 1] * 0.125f;
    const float ubx = mb[pi * 2 + 0] * 0.125f;
    const float uby = mb[pi * 2 + 1] * 0.125f;
    const float xsx = 2.0f * nz[pi * 2 + 0] - 1.0f + ubx;
    const float xsy = 2.0f * nz[pi * 2 + 1] - 1.0f + uby;

    // ---- F_a bilinear setup ----
    const float fax0 = floorf(xa), fay0 = floorf(ya);
    const float wxa = xa - fax0, wya = ya - fay0;
    int ax0 = min(max((int)fax0, 0), WW - 1);
    int ax1 = min(ax0 + 1, WW - 1);
    int ay0 = min(max((int)fay0, 0), HH - 1);
    int ay1 = min(ay0 + 1, HH - 1);
    const float wa00 = (1.f - wxa) * (1.f - wya);
    const float wa01 = wxa * (1.f - wya);
    const float wa10 = (1.f - wxa) * wya;
    const float wa11 = wxa * wya;
    const int aoff00 = ay0 * WW + ax0, aoff01 = ay0 * WW + ax1;
    const int aoff10 = ay1 * WW + ax0, aoff11 = ay1 * WW + ax1;

    // ---- F_b bilinear + on-the-fly gradient setup ----
    const float fbx0 = floorf(xsx), fby0 = floorf(xsy);
    const float wxb = xsx - fbx0, wyb = xsy - fby0;
    int bx0 = min(max((int)fbx0, 0), WW - 1);
    int bx1 = min(bx0 + 1, WW - 1);
    int by0 = min(max((int)fby0, 0), HH - 1);
    int by1 = min(by0 + 1, HH - 1);
    int cxs0 = max(bx0 - 1, 0);
    int cxs3 = min(bx1 + 1, WW - 1);
    int rys0 = max(by0 - 1, 0);
    int rys3 = min(by1 + 1, HH - 1);
    const int sx = (bx1 > bx0) ? 1 : 0;
    const int sy = (by1 > by0) ? 1 : 0;
    const float wb00 = (1.f - wxb) * (1.f - wyb);
    const float wb01 = wxb * (1.f - wyb);
    const float wb10 = (1.f - wxb) * wyb;
    const float wb11 = wxb * wyb;

    int cxs[4]  = { cxs0, bx0, bx1, cxs3 };
    int roff[4] = { rys0 * WW, by0 * WW, by1 * WW, rys3 * WW };

    const float* __restrict__ FaB = Fa + (size_t)b * CC * HWSZ;
    const float* __restrict__ FbB = Fb + (size_t)b * CC * HWSZ;

    // ---- channel accumulation: this warp covers channels [half*64, half*64+64) ----
    float s_tt = 0.f, s_ss = 0.f, s_xs = 0.f, s_xt = 0.f, s_ys = 0.f,
          s_yt = 0.f, s_xx = 0.f, s_xy = 0.f, s_yy = 0.f;

    #pragma unroll
    for (int it = 0; it < 2; it++) {
        const int cc = half * 64 + it * 32 + lane;
        const float* p = FbB + cc * HWSZ;
        float v[4][4];
        #pragma unroll
        for (int r = 0; r < 4; r++) {
            #pragma unroll
            for (int k = 0; k < 4; k++)
                v[r][k] = __ldg(p + roff[r] + cxs[k]);
        }
        const float* pa = FaB + cc * HWSZ;
        const float a00 = __ldg(pa + aoff00);
        const float a01 = __ldg(pa + aoff01);
        const float a10 = __ldg(pa + aoff10);
        const float a11 = __ldg(pa + aoff11);

        const float fs = wb00 * v[1][1] + wb01 * v[1][2] + wb10 * v[2][1] + wb11 * v[2][2];
        const float Jx = 0.5f * (wb00 * (v[1][2] - v[1][0]) + wb01 * (v[1][3] - v[1][sx]) +
                                 wb10 * (v[2][2] - v[2][0]) + wb11 * (v[2][3] - v[2][sx]));
        const float Jy = 0.5f * (wb00 * (v[2][1] - v[0][1]) + wb01 * (v[2][2] - v[0][2]) +
                                 wb10 * (v[3][1] - v[sy][1]) + wb11 * (v[3][2] - v[sy][2]));
        const float ft = wa00 * a00 + wa01 * a01 + wa10 * a10 + wa11 * a11;

        s_tt += ft * ft;  s_ss += fs * fs;
        s_xs += Jx * fs;  s_xt += Jx * ft;
        s_ys += Jy * fs;  s_yt += Jy * ft;
        s_xx += Jx * Jx;  s_xy += Jx * Jy;  s_yy += Jy * Jy;
    }

    // ---- warp reduction of the 9 sums ----
    #pragma unroll
    for (int o = 16; o > 0; o >>= 1) {
        s_tt += __shfl_xor_sync(0xFFFFFFFFu, s_tt, o);
        s_ss += __shfl_xor_sync(0xFFFFFFFFu, s_ss, o);
        s_xs += __shfl_xor_sync(0xFFFFFFFFu, s_xs, o);
        s_xt += __shfl_xor_sync(0xFFFFFFFFu, s_xt, o);
        s_ys += __shfl_xor_sync(0xFFFFFFFFu, s_ys, o);
        s_yt += __shfl_xor_sync(0xFFFFFFFFu, s_yt, o);
        s_xx += __shfl_xor_sync(0xFFFFFFFFu, s_xx, o);
        s_xy += __shfl_xor_sync(0xFFFFFFFFu, s_xy, o);
        s_yy += __shfl_xor_sync(0xFFFFFFFFu, s_yy, o);
    }

    // ---- combine warp pairs, per-point epilogue, per-block partial ----
    __shared__ float s9[8][12];      // 9 sums per warp, padded
    __shared__ double sh_e1[PTS_PER_BLOCK];
    __shared__ double sh_ld[PTS_PER_BLOCK];

    if (lane == 0) {
        s9[w][0] = s_tt; s9[w][1] = s_ss; s9[w][2] = s_xs; s9[w][3] = s_xt;
        s9[w][4] = s_ys; s9[w][5] = s_yt; s9[w][6] = s_xx; s9[w][7] = s_xy;
        s9[w][8] = s_yy;
    }
    __syncthreads();

    if (half == 0 && lane == 0) {
        const float t_tt = s9[w][0] + s9[w+1][0];
        const float t_ss = s9[w][1] + s9[w+1][1];
        const float t_xs = s9[w][2] + s9[w+1][2];
        const float t_xt = s9[w][3] + s9[w+1][3];
        const float t_ys = s9[w][4] + s9[w+1][4];
        const float t_yt = s9[w][5] + s9[w+1][5];
        const float t_xx = s9[w][6] + s9[w+1][6];
        const float t_xy = s9[w][7] + s9[w+1][7];
        const float t_yy = s9[w][8] + s9[w+1][8];

        const float invnt = 1.f / fmaxf(sqrtf(t_tt), 1e-12f);
        const float invns = 1.f / fmaxf(sqrtf(t_ss), 1e-12f);
        const float bxv = t_xs * invns - t_xt * invnt;
        const float byv = t_ys * invns - t_yt * invnt;
        const float aH = t_xx + EPSV;
        const float dH = t_yy + EPSV;
        const float bH = t_xy;
        const float det = aH * dH - bH * bH;
        const float inv_det = 1.f / det;
        const float ddx = (dH * bxv - bH * byv) * inv_det;
        const float ddy = (aH * byv - bH * bxv) * inv_det;
        const float dx = (ubx - xsx) + ddx;
        const float dy = (uby - xsy) + ddy;
        sh_e1[q] = 0.5 * (double)(aH * dx * dx + 2.f * bH * dx * dy + dH * dy * dy);
        sh_ld[q] = log((double)det);
    }
    __syncthreads();

    if (threadIdx.x == 0) {
        double e1 = 0.0, ld = 0.0;
        #pragma unroll
        for (int i = 0; i < PTS_PER_BLOCK; i++) { e1 += sh_e1[i]; ld += sh_ld[i]; }
        g_pe1[blockIdx.x] = e1;
        g_pld[blockIdx.x] = ld;
    }
}

__global__ __launch_bounds__(256) void gn_finalize_kernel(float* __restrict__ out) {
    const int t = threadIdx.x;
    double e1 = 0.0, ld = 0.0;
    #pragma unroll
    for (int i = 0; i < NBLOCKS; i += 256) {
        e1 += g_pe1[t + i];
        ld += g_pld[t + i];
    }
    __shared__ double se1[256];
    __shared__ double sld[256];
    se1[t] = e1; sld[t] = ld;
    __syncthreads();
    #pragma unroll
    for (int s = 128; s > 0; s >>= 1) {
        if (t < s) { se1[t] += se1[t + s]; sld[t] += sld[t + s]; }
        __syncthreads();
    }
    if (t == 0) {
        const double E1 = se1[0];
        const double E2 = (double)NPTS * log(2.0 * M_PI) - 0.5 * sld[0];
        const double E  = E1 + (2.0 / 7.0) * E2;
        out[0] = (float)(0.3 * E);
        out[1] = (float)E1;
        out[2] = (float)E2;
    }
}

extern "C" void kernel_launch(void* const* d_in, const int* in_sizes, int n_in,
                              void* d_out, int out_size) {
    const float* Fa = (const float*)d_in[0];
    const float* Fb = (const float*)d_in[1];
    const float* ma = (const float*)d_in[2];
    const float* mb = (const float*)d_in[3];
    const float* nz = (const float*)d_in[4];
    float* out = (float*)d_out;

    gn_main_kernel<<<NBLOCKS, 256>>>(Fa, Fb, ma, mb, nz);
    gn_finalize_kernel<<<1, 256>>>(out);
}